// round 4
// baseline (speedup 1.0000x reference)
#include <cuda_runtime.h>

// Problem constants (from reference): N=100000, E=1600000, D=128, H=256, C=40
#define NN 100000
#define EE 1600000
#define DD 128
#define HH 256
#define CC 40

// ---------------- scratch (static device globals; no allocation allowed) ----
__device__ float g_rst[(size_t)NN * HH];   // aggregation result / GEMM input
__device__ float g_t[(size_t)NN * HH];     // hidden after first MLP matmul
__device__ float g_h[(size_t)NN * HH];     // layer output
__device__ int   g_rowstart[NN + 1];
__device__ int   g_cursor[NN];
__device__ int   g_csr[EE];

// ---------------- CSR build ------------------------------------------------
__global__ void hist_kernel(const int* __restrict__ dst, int* __restrict__ cnt, int e) {
    int i = blockIdx.x * blockDim.x + threadIdx.x;
    if (i < e) atomicAdd(&cnt[dst[i]], 1);
}

// Single-block exclusive scan over n counters. In-place: cnt_cursor becomes the
// running cursor (== exclusive prefix), row_start gets the exclusive prefix and
// row_start[n] = total.
__global__ void scan_kernel(int* __restrict__ cnt_cursor, int* __restrict__ row_start, int n) {
    __shared__ int wsum[32];
    __shared__ int carry;
    const int tid = threadIdx.x;
    const int lane = tid & 31;
    const int wid = tid >> 5;
    if (tid == 0) carry = 0;
    __syncthreads();
    for (int base = 0; base < n; base += 1024) {
        int i = base + tid;
        int v = (i < n) ? cnt_cursor[i] : 0;
        int x = v;
        #pragma unroll
        for (int o = 1; o < 32; o <<= 1) {
            int y = __shfl_up_sync(0xffffffffu, x, o);
            if (lane >= o) x += y;
        }
        if (lane == 31) wsum[wid] = x;
        __syncthreads();
        if (wid == 0) {
            int wv = wsum[lane];
            #pragma unroll
            for (int o = 1; o < 32; o <<= 1) {
                int y = __shfl_up_sync(0xffffffffu, wv, o);
                if (lane >= o) wv += y;
            }
            wsum[lane] = wv;
        }
        __syncthreads();
        int excl = x - v + (wid ? wsum[wid - 1] : 0) + carry;
        if (i < n) { row_start[i] = excl; cnt_cursor[i] = excl; }
        if (i == n - 1) row_start[n] = excl + v;
        __syncthreads();
        if (tid == 0) carry += wsum[31];
        __syncthreads();
    }
}

__global__ void fill_kernel(const int* __restrict__ src, const int* __restrict__ dst,
                            int* __restrict__ cursor, int* __restrict__ csr, int e) {
    int i = blockIdx.x * blockDim.x + threadIdx.x;
    if (i < e) {
        int p = atomicAdd(&cursor[dst[i]], 1);
        csr[p] = src[i];
    }
}

// ---------------- aggregation: rst = (1+eps)*h + sum_{edges dst==v} h[src] --
// One warp per node; lane owns DIM/32 columns as float4s. Gather-based, no atomics.
template <int DIM>
__global__ __launch_bounds__(256) void agg_kernel(
    const float4* __restrict__ h, const int* __restrict__ rs,
    const int* __restrict__ csr, const float* __restrict__ eps,
    float4* __restrict__ out, int n)
{
    int w = (blockIdx.x * 256 + threadIdx.x) >> 5;
    if (w >= n) return;
    int lane = threadIdx.x & 31;
    constexpr int V = DIM / 128;  // float4s per lane
    float s = 1.0f + *eps;
    size_t base = (size_t)w * (DIM / 4);
    float4 acc[V];
    #pragma unroll
    for (int j = 0; j < V; j++) {
        float4 v = h[base + lane + 32 * j];
        acc[j] = make_float4(v.x * s, v.y * s, v.z * s, v.w * s);
    }
    int e0 = rs[w], e1 = rs[w + 1];
    for (int e = e0; e < e1; e++) {
        size_t b2 = (size_t)csr[e] * (DIM / 4);
        #pragma unroll
        for (int j = 0; j < V; j++) {
            float4 v = h[b2 + lane + 32 * j];
            acc[j].x += v.x; acc[j].y += v.y; acc[j].z += v.z; acc[j].w += v.w;
        }
    }
    #pragma unroll
    for (int j = 0; j < V; j++) out[base + lane + 32 * j] = acc[j];
}

// ---------------- packed f32x2 helpers (FFMA2 — 2x fp32 throughput) --------
__device__ __forceinline__ unsigned long long rep2(float x) {
    unsigned long long r;
    asm("mov.b64 %0, {%1, %1};" : "=l"(r) : "f"(x));
    return r;
}
__device__ __forceinline__ float2 unpk2(unsigned long long u) {
    float2 f;
    asm("mov.b64 {%0, %1}, %2;" : "=f"(f.x), "=f"(f.y) : "l"(u));
    return f;
}
__device__ __forceinline__ void fma2(unsigned long long& d, unsigned long long a, unsigned long long b) {
    asm("fma.rn.f32x2 %0, %1, %2, %0;" : "+l"(d) : "l"(a), "l"(b));
}

// ---------------- GEMM: C[n,M] = act(A[n,K] @ B[K,M] (+bias)) ---------------
// BM=128, BN=64, BK=16, 256 threads. Per thread: 8 rows x 4 cols, accumulated
// as 16 packed f32x2 pairs (row pairs) -> 16 FFMA2 per k-step.
template <bool RELU, bool BIAS>
__global__ __launch_bounds__(256) void gemm_kernel(
    const float* __restrict__ A, const float* __restrict__ B,
    const float* __restrict__ bias, float* __restrict__ C,
    int n, int K, int M)
{
    constexpr int BM = 128, BN = 64, BK = 16, AS = 132;  // padded stride
    __shared__ float As[BK * AS];   // As[k][m], transposed for contiguous frags
    __shared__ float Bs[BK * BN];   // Bs[k][m]
    const int tid = threadIdx.x;
    const int tx = tid & 15;        // col group: 4 cols
    const int ty = tid >> 4;        // row group: 8 rows
    const int n0 = blockIdx.x * BM;
    const int m0 = blockIdx.y * BN;
    const int rowA = tid >> 2;          // 0..63
    const int colA = (tid & 3) << 2;    // 0,4,8,12
    const int rowB = tid >> 4;          // 0..15
    const int colB = (tid & 15) << 2;   // 0..60

    unsigned long long acc[4][4];
    #pragma unroll
    for (int i = 0; i < 4; i++)
        #pragma unroll
        for (int j = 0; j < 4; j++) acc[i][j] = 0ull;

    for (int k0 = 0; k0 < K; k0 += BK) {
        // A tile load (2 float4 rows per thread), transposed store into As
        #pragma unroll
        for (int r = 0; r < 2; r++) {
            int row = rowA + r * 64;
            int g = n0 + row;
            float4 v = make_float4(0.f, 0.f, 0.f, 0.f);
            if (g < n) v = *(const float4*)(A + (size_t)g * K + k0 + colA);
            As[(colA + 0) * AS + row] = v.x;
            As[(colA + 1) * AS + row] = v.y;
            As[(colA + 2) * AS + row] = v.z;
            As[(colA + 3) * AS + row] = v.w;
        }
        // B tile load (1 float4 per thread), vector-granular M guard (M % 4 == 0)
        {
            int gm = m0 + colB;
            float4 v = make_float4(0.f, 0.f, 0.f, 0.f);
            if (gm + 3 < M) v = *(const float4*)(B + (size_t)(k0 + rowB) * M + gm);
            *(float4*)(Bs + rowB * BN + colB) = v;
        }
        __syncthreads();
        #pragma unroll
        for (int k = 0; k < BK; k++) {
            const float* as = As + k * AS + ty * 8;
            unsigned long long a0 = *(const unsigned long long*)(as + 0);
            unsigned long long a1 = *(const unsigned long long*)(as + 2);
            unsigned long long a2 = *(const unsigned long long*)(as + 4);
            unsigned long long a3 = *(const unsigned long long*)(as + 6);
            float4 b = *(const float4*)(Bs + k * BN + tx * 4);
            unsigned long long b0 = rep2(b.x), b1 = rep2(b.y), b2 = rep2(b.z), b3 = rep2(b.w);
            fma2(acc[0][0], a0, b0); fma2(acc[0][1], a0, b1); fma2(acc[0][2], a0, b2); fma2(acc[0][3], a0, b3);
            fma2(acc[1][0], a1, b0); fma2(acc[1][1], a1, b1); fma2(acc[1][2], a1, b2); fma2(acc[1][3], a1, b3);
            fma2(acc[2][0], a2, b0); fma2(acc[2][1], a2, b1); fma2(acc[2][2], a2, b2); fma2(acc[2][3], a2, b3);
            fma2(acc[3][0], a3, b0); fma2(acc[3][1], a3, b1); fma2(acc[3][2], a3, b2); fma2(acc[3][3], a3, b3);
        }
        __syncthreads();
    }

    // Epilogue: acc[i4][j] holds rows (ty*8 + 2*i4, +1), col tx*4 + j
    #pragma unroll
    for (int i4 = 0; i4 < 4; i4++) {
        float2 p[4];
        #pragma unroll
        for (int j = 0; j < 4; j++) p[j] = unpk2(acc[i4][j]);
        #pragma unroll
        for (int hh = 0; hh < 2; hh++) {
            int row = n0 + ty * 8 + i4 * 2 + hh;
            if (row >= n) continue;
            float vals[4];
            vals[0] = hh ? p[0].y : p[0].x;
            vals[1] = hh ? p[1].y : p[1].x;
            vals[2] = hh ? p[2].y : p[2].x;
            vals[3] = hh ? p[3].y : p[3].x;
            int col0 = m0 + tx * 4;
            #pragma unroll
            for (int j = 0; j < 4; j++) {
                if (BIAS && (col0 + j < M)) vals[j] += bias[col0 + j];
                if (RELU) vals[j] = fmaxf(vals[j], 0.f);
            }
            if (col0 + 3 < M) {
                *(float4*)(C + (size_t)row * M + col0) =
                    make_float4(vals[0], vals[1], vals[2], vals[3]);
            } else {
                #pragma unroll
                for (int j = 0; j < 4; j++)
                    if (col0 + j < M) C[(size_t)row * M + col0 + j] = vals[j];
            }
        }
    }
}

// ---------------- launch ----------------------------------------------------
extern "C" void kernel_launch(void* const* d_in, const int* in_sizes, int n_in,
                              void* d_out, int out_size) {
    const float* x    = (const float*)d_in[0];
    const int*   src  = (const int*)d_in[1];
    const int*   dst  = (const int*)d_in[2];
    const float* eps1 = (const float*)d_in[3];
    const float* w1a  = (const float*)d_in[4];
    const float* w1b  = (const float*)d_in[5];
    const float* eps2 = (const float*)d_in[6];
    const float* w2a  = (const float*)d_in[7];
    const float* w2b  = (const float*)d_in[8];
    const float* fcw  = (const float*)d_in[9];
    const float* fcb  = (const float*)d_in[10];
    float* out = (float*)d_out;

    const int n = in_sizes[0] / DD;   // 100000
    const int e = in_sizes[1];        // 1600000

    float *rst, *t, *h;
    int *rs, *cur, *csr;
    cudaGetSymbolAddress((void**)&rst, g_rst);
    cudaGetSymbolAddress((void**)&t,   g_t);
    cudaGetSymbolAddress((void**)&h,   g_h);
    cudaGetSymbolAddress((void**)&rs,  g_rowstart);
    cudaGetSymbolAddress((void**)&cur, g_cursor);
    cudaGetSymbolAddress((void**)&csr, g_csr);

    // --- build CSR (dst-grouped) each call; gather-based aggregation after ---
    cudaMemsetAsync(cur, 0, (size_t)n * sizeof(int));
    int eb = (e + 255) / 256;
    hist_kernel<<<eb, 256>>>(dst, cur, e);
    scan_kernel<<<1, 1024>>>(cur, rs, n);
    fill_kernel<<<eb, 256>>>(src, dst, cur, csr, e);

    const int aggBlocks = (n + 7) / 8;  // 8 warps / block, 1 warp / node
    dim3 gFull((n + 127) / 128, HH / 64);
    dim3 gFc((n + 127) / 128, 1);

    // Layer 1
    agg_kernel<DD><<<aggBlocks, 256>>>((const float4*)x, rs, csr, eps1, (float4*)rst, n);
    gemm_kernel<true,  false><<<gFull, 256>>>(rst, w1a, nullptr, t, n, DD, HH);
    gemm_kernel<true,  false><<<gFull, 256>>>(t,   w1b, nullptr, h, n, HH, HH);
    // Layer 2
    agg_kernel<HH><<<aggBlocks, 256>>>((const float4*)h, rs, csr, eps2, (float4*)rst, n);
    gemm_kernel<true,  false><<<gFull, 256>>>(rst, w2a, nullptr, t, n, HH, HH);
    gemm_kernel<true,  false><<<gFull, 256>>>(t,   w2b, nullptr, h, n, HH, HH);
    // Classifier
    gemm_kernel<false, true ><<<gFc,   256>>>(h,   fcw, fcb,     out, n, HH, CC);
}